// round 15
// baseline (speedup 1.0000x reference)
#include <cuda_runtime.h>

#define NMAX 100000
#define EMAX 3200000
#define CAP  128   // per-node CSR slab; deg~Poisson(32), P(deg>128) ~ 1e-40

// ---- device scratch (no allocations allowed) ----
__device__ float g_dinv [NMAX];
__device__ int   g_cnt  [NMAX];
__device__ unsigned long long g_csr[(size_t)NMAX * CAP];  // (w_bits<<32 | row)
__device__ float g_h1raw[NMAX * 16];         // x@W1 (unscaled)
__device__ float g_h1s  [NMAX * 16];         // (x@W1) * dinv[node]
__device__ float g_r    [NMAX * 16];         // relu(layer1)*dinv (scaled)
__device__ int   g_is64;

// kernel 1: detect int64-vs-int32 edge_index + zero per-node counters
__global__ void initdet_kernel(const unsigned int* __restrict__ idx, int n) {
    int i = blockIdx.x * blockDim.x + threadIdx.x;
    if (i < n) g_cnt[i] = 0;
    if (blockIdx.x == 0) {
        __shared__ int found;
        if (threadIdx.x == 0) found = 0;
        __syncthreads();
        for (int j = threadIdx.x; j < 2048; j += blockDim.x) {
            if (idx[2 * j + 1] != 0u) found = 1;
        }
        __syncthreads();
        if (threadIdx.x == 0) g_is64 = (found == 0);
    }
}

// kernel 2 (FUSED): blockIdx < gemmBlocks  -> GEMM tile (h1raw = x @ W1)
//                   blockIdx >= gemmBlocks -> scatter chunk (CSR build)
// The two halves use disjoint resources (FMA/LDS/DRAM-stream vs L2-atomics),
// so co-residency on each SM overlaps them without streams.
__global__ __launch_bounds__(128) void fused_kernel(const float* __restrict__ x,
                                                    const float* __restrict__ W1,
                                                    const void* __restrict__ idxv,
                                                    const float* __restrict__ w,
                                                    int n, int E, int gemmBlocks) {
    __shared__ float Ws[256 * 16];     // 16 KB
    __shared__ float xs[16][257];      // 16.4 KB

    if (blockIdx.x >= gemmBlocks) {
        // ---- scatter branch ----
        int e = (blockIdx.x - gemmBlocks) * 128 + threadIdx.x;
        if (e >= E) return;
        int row, col;
        if (g_is64) {
            const long long* p = (const long long*)idxv;
            row = (int)p[e];
            col = (int)p[(size_t)E + e];
        } else {
            const int* p = (const int*)idxv;
            row = p[e];
            col = p[E + e];
        }
        int r = atomicAdd(&g_cnt[col], 1);
        if (r < CAP)
            g_csr[(size_t)col * CAP + r] =
                ((unsigned long long)__float_as_uint(w[e]) << 32) | (unsigned int)row;
        return;
    }

    // ---- GEMM branch: 128 threads / 256-node tile, 2 nodes per thread ----
    int t = threadIdx.x;
    int node0 = blockIdx.x * 256;
    {
        const float4* W4 = (const float4*)W1;
        float4* Ws4 = (float4*)Ws;
#pragma unroll
        for (int j = 0; j < 8; j++) Ws4[t + 128 * j] = W4[t + 128 * j];
    }
    float accA[16], accB[16];
#pragma unroll
    for (int o = 0; o < 16; o++) { accA[o] = 0.f; accB[o] = 0.f; }

    for (int kk = 0; kk < 256; kk += 16) {
        __syncthreads();
#pragma unroll
        for (int j = 0; j < 8; j++) {
            int i4 = t + 128 * j;        // 1024 float4 slots = 256 nodes x 16 floats
            int nloc = i4 >> 2;
            int k4 = (i4 & 3) * 4;
            int nn = node0 + nloc;
            float4 v = (nn < n) ? *(const float4*)&x[(size_t)nn * 256 + kk + k4]
                                : make_float4(0.f, 0.f, 0.f, 0.f);
            xs[k4 + 0][nloc] = v.x;
            xs[k4 + 1][nloc] = v.y;
            xs[k4 + 2][nloc] = v.z;
            xs[k4 + 3][nloc] = v.w;
        }
        __syncthreads();
#pragma unroll
        for (int k = 0; k < 16; k++) {
            float xa = xs[k][t];
            float xb = xs[k][t + 128];
            const float4* wr = (const float4*)&Ws[(kk + k) * 16];
            float4 w0 = wr[0], w1 = wr[1], w2 = wr[2], w3 = wr[3];
            accA[0]  += xa * w0.x; accA[1]  += xa * w0.y; accA[2]  += xa * w0.z; accA[3]  += xa * w0.w;
            accA[4]  += xa * w1.x; accA[5]  += xa * w1.y; accA[6]  += xa * w1.z; accA[7]  += xa * w1.w;
            accA[8]  += xa * w2.x; accA[9]  += xa * w2.y; accA[10] += xa * w2.z; accA[11] += xa * w2.w;
            accA[12] += xa * w3.x; accA[13] += xa * w3.y; accA[14] += xa * w3.z; accA[15] += xa * w3.w;
            accB[0]  += xb * w0.x; accB[1]  += xb * w0.y; accB[2]  += xb * w0.z; accB[3]  += xb * w0.w;
            accB[4]  += xb * w1.x; accB[5]  += xb * w1.y; accB[6]  += xb * w1.z; accB[7]  += xb * w1.w;
            accB[8]  += xb * w2.x; accB[9]  += xb * w2.y; accB[10] += xb * w2.z; accB[11] += xb * w2.w;
            accB[12] += xb * w3.x; accB[13] += xb * w3.y; accB[14] += xb * w3.z; accB[15] += xb * w3.w;
        }
    }
    int nodeA = node0 + t;
    if (nodeA < n) {
        float4* hp = (float4*)(g_h1raw + (size_t)nodeA * 16);
#pragma unroll
        for (int q = 0; q < 4; q++)
            hp[q] = make_float4(accA[4 * q], accA[4 * q + 1], accA[4 * q + 2], accA[4 * q + 3]);
    }
    int nodeB = node0 + t + 128;
    if (nodeB < n) {
        float4* hp = (float4*)(g_h1raw + (size_t)nodeB * 16);
#pragma unroll
        for (int q = 0; q < 4; q++)
            hp[q] = make_float4(accB[4 * q], accB[4 * q + 1], accB[4 * q + 2], accB[4 * q + 3]);
    }
}

// kernel 3: weighted degree from slab (warp per node, coalesced) -> dinv
__global__ __launch_bounds__(256) void deg_kernel(int n) {
    int node = (blockIdx.x * blockDim.x + threadIdx.x) >> 5;
    if (node >= n) return;
    int lane = threadIdx.x & 31;
    int cnt = min(g_cnt[node], CAP);
    size_t base = (size_t)node * CAP;
    float s = 0.f;
    for (int e = lane; e < cnt; e += 32)
        s += __uint_as_float((unsigned int)(g_csr[base + e] >> 32));
#pragma unroll
    for (int d = 16; d > 0; d >>= 1)
        s += __shfl_xor_sync(0xffffffff, s, d);
    if (lane == 0) g_dinv[node] = rsqrtf(1.0f + s);   // +1 = self-loop weight
}

// kernel 4: h1s = h1raw * dinv  (separate buffer: graph replays must be idempotent)
__global__ __launch_bounds__(256) void scale_kernel(int n) {
    int node = blockIdx.x * blockDim.x + threadIdx.x;
    if (node >= n) return;
    float di = g_dinv[node];
    const float4* rp = (const float4*)(g_h1raw + (size_t)node * 16);
    float4* sp = (float4*)(g_h1s + (size_t)node * 16);
#pragma unroll
    for (int q = 0; q < 4; q++) {
        float4 v = rp[q];
        sp[q] = make_float4(v.x * di, v.y * di, v.z * di, v.w * di);
    }
}

// kernel 5: layer-1 aggregation. One warp per node, 8 edge-slots x 4 feature-lanes.
// r' = relu(dinv*(sum_e h1s[row]*w + h1s[self]) + b1) * dinv
__global__ __launch_bounds__(256) void agg1_kernel(const float* __restrict__ b1, int n) {
    int node = (blockIdx.x * blockDim.x + threadIdx.x) >> 5;
    if (node >= n) return;
    int lane = threadIdx.x & 31;
    int es = lane >> 2, f = lane & 3;

    size_t base = (size_t)node * CAP;
    int cnt = min(g_cnt[node], CAP);
    float4 acc = make_float4(0.f, 0.f, 0.f, 0.f);
    for (int e = es; e < cnt; e += 8) {
        unsigned long long v = g_csr[base + e];
        int row = (int)(unsigned int)(v & 0xffffffffu);
        float w = __uint_as_float((unsigned int)(v >> 32));
        float4 h = ((const float4*)(g_h1s + (size_t)row * 16))[f];
        acc.x += h.x * w; acc.y += h.y * w;
        acc.z += h.z * w; acc.w += h.w * w;
    }
#pragma unroll
    for (int s = 16; s >= 4; s >>= 1) {
        acc.x += __shfl_down_sync(0xffffffff, acc.x, s);
        acc.y += __shfl_down_sync(0xffffffff, acc.y, s);
        acc.z += __shfl_down_sync(0xffffffff, acc.z, s);
        acc.w += __shfl_down_sync(0xffffffff, acc.w, s);
    }
    if (es == 0) {
        float di = g_dinv[node];
        float4 h = ((const float4*)(g_h1s + (size_t)node * 16))[f];
        float4 b = ((const float4*)b1)[f];
        acc.x = fmaxf((acc.x + h.x) * di + b.x, 0.f) * di;
        acc.y = fmaxf((acc.y + h.y) * di + b.y, 0.f) * di;
        acc.z = fmaxf((acc.z + h.z) * di + b.z, 0.f) * di;
        acc.w = fmaxf((acc.w + h.w) * di + b.w, 0.f) * di;
        ((float4*)(g_r + (size_t)node * 16))[f] = acc;
    }
}

// kernel 6: layer-2 aggregation fused with W2 GEMM + log_softmax.
__global__ __launch_bounds__(256) void agg2final_kernel(const float* __restrict__ W2,
                                                        const float* __restrict__ b2,
                                                        float* __restrict__ out, int n) {
    __shared__ float W2s[16 * 40];
    __shared__ float b2s[40];
    __shared__ float sh[8][16];
    int t = threadIdx.x;
    for (int i = t; i < 640; i += 256) W2s[i] = W2[i];
    if (t < 40) b2s[t] = b2[t];
    __syncthreads();

    int warp = t >> 5;
    int lane = t & 31;
    int node = blockIdx.x * 8 + warp;
    if (node >= n) return;
    int es = lane >> 2, f = lane & 3;

    size_t base = (size_t)node * CAP;
    int cnt = min(g_cnt[node], CAP);
    float4 acc = make_float4(0.f, 0.f, 0.f, 0.f);
    for (int e = es; e < cnt; e += 8) {
        unsigned long long v = g_csr[base + e];
        int row = (int)(unsigned int)(v & 0xffffffffu);
        float w = __uint_as_float((unsigned int)(v >> 32));
        float4 h = ((const float4*)(g_r + (size_t)row * 16))[f];
        acc.x += h.x * w; acc.y += h.y * w;
        acc.z += h.z * w; acc.w += h.w * w;
    }
#pragma unroll
    for (int s = 16; s >= 4; s >>= 1) {
        acc.x += __shfl_down_sync(0xffffffff, acc.x, s);
        acc.y += __shfl_down_sync(0xffffffff, acc.y, s);
        acc.z += __shfl_down_sync(0xffffffff, acc.z, s);
        acc.w += __shfl_down_sync(0xffffffff, acc.w, s);
    }
    if (es == 0) {
        float di = g_dinv[node];
        float4 h = ((const float4*)(g_r + (size_t)node * 16))[f];
        acc.x = (acc.x + h.x) * di;
        acc.y = (acc.y + h.y) * di;
        acc.z = (acc.z + h.z) * di;
        acc.w = (acc.w + h.w) * di;
        ((float4*)&sh[warp][0])[f] = acc;
    }
    __syncwarp();

    // 40 logits distributed over the warp (lane -> out[lane], lane<8 -> out[lane+32])
    float v0 = b2s[lane];
    float v1 = (lane < 8) ? b2s[lane + 32] : -1e30f;
#pragma unroll
    for (int k = 0; k < 16; k++) {
        float hv = sh[warp][k];
        v0 += hv * W2s[k * 40 + lane];
        if (lane < 8) v1 += hv * W2s[k * 40 + lane + 32];
    }
    float m = fmaxf(v0, v1);
#pragma unroll
    for (int s = 16; s > 0; s >>= 1)
        m = fmaxf(m, __shfl_xor_sync(0xffffffff, m, s));
    float sum = __expf(v0 - m) + ((lane < 8) ? __expf(v1 - m) : 0.f);
#pragma unroll
    for (int s = 16; s > 0; s >>= 1)
        sum += __shfl_xor_sync(0xffffffff, sum, s);
    float l = m + __logf(sum);
    out[(size_t)node * 40 + lane] = v0 - l;
    if (lane < 8) out[(size_t)node * 40 + 32 + lane] = v1 - l;
}

extern "C" void kernel_launch(void* const* d_in, const int* in_sizes, int n_in,
                              void* d_out, int out_size) {
    const float* x  = (const float*)d_in[0];
    const void*  ei = d_in[1];
    const float* ew = (const float*)d_in[2];
    const float* W1 = (const float*)d_in[3];
    const float* b1 = (const float*)d_in[4];
    const float* W2 = (const float*)d_in[5];
    const float* b2 = (const float*)d_in[6];
    float* out = (float*)d_out;

    int n = in_sizes[0] / 256;   // N nodes
    int E = in_sizes[2];         // edges

    int nb = (n + 255) / 256;
    int gemmBlocks    = (n + 255) / 256;
    int scatterBlocks = (E + 127) / 128;

    initdet_kernel<<<nb, 256>>>((const unsigned int*)ei, n);
    fused_kernel<<<gemmBlocks + scatterBlocks, 128>>>(x, W1, ei, ew, n, E, gemmBlocks);
    deg_kernel<<<(n + 7) / 8, 256>>>(n);
    scale_kernel<<<nb, 256>>>(n);
    agg1_kernel<<<(n + 7) / 8, 256>>>(b1, n);
    agg2final_kernel<<<(n + 7) / 8, 256>>>(W2, b2, out, n);
}

// round 16
// speedup vs baseline: 1.1806x; 1.1806x over previous
#include <cuda_runtime.h>

#define NMAX 100000
#define EMAX 3200000
#define CAP  128   // per-node CSR slab; deg~Poisson(32), P(deg>128) ~ 1e-40

// ---- device scratch (no allocations allowed) ----
__device__ float g_dinv [NMAX];
__device__ int   g_cnt  [NMAX];
__device__ unsigned long long g_csr[(size_t)NMAX * CAP];  // (w_bits<<32 | row)
__device__ float g_h1raw[NMAX * 16];         // x@W1 (unscaled)
__device__ float g_h1s  [NMAX * 16];         // (x@W1) * dinv[node]
__device__ float g_r    [NMAX * 16];         // relu(layer1)*dinv (scaled)
__device__ int   g_is64;

// kernel 1: detect int64-vs-int32 edge_index + zero per-node counters
__global__ void initdet_kernel(const unsigned int* __restrict__ idx, int n) {
    int i = blockIdx.x * blockDim.x + threadIdx.x;
    if (i < n) g_cnt[i] = 0;
    if (blockIdx.x == 0) {
        __shared__ int found;
        if (threadIdx.x == 0) found = 0;
        __syncthreads();
        for (int j = threadIdx.x; j < 2048; j += blockDim.x) {
            if (idx[2 * j + 1] != 0u) found = 1;
        }
        __syncthreads();
        if (threadIdx.x == 0) g_is64 = (found == 0);
    }
}

// kernel 2: h1raw = x @ W1 (no dinv dependency). Triggers PDL early so the
// scatter kernel (launched with programmaticStreamSerialization) co-resides:
// gemm blocks use FMA/LDS/DRAM-stream, scatter warps fill remaining thread
// slots and drive L2 atomics/stores — disjoint resources, true overlap.
__global__ __launch_bounds__(128) void gemmraw_kernel(const float* __restrict__ x,
                                                      const float* __restrict__ W1, int n) {
#if __CUDA_ARCH__ >= 900
    asm volatile("griddepcontrol.launch_dependents;");
#endif
    __shared__ float Ws[256 * 16];     // 16 KB
    __shared__ float xs[16][257];      // 16.4 KB
    int t = threadIdx.x;
    int node0 = blockIdx.x * 256;
    {
        const float4* W4 = (const float4*)W1;
        float4* Ws4 = (float4*)Ws;
#pragma unroll
        for (int j = 0; j < 8; j++) Ws4[t + 128 * j] = W4[t + 128 * j];
    }
    float accA[16], accB[16];
#pragma unroll
    for (int o = 0; o < 16; o++) { accA[o] = 0.f; accB[o] = 0.f; }

    for (int kk = 0; kk < 256; kk += 16) {
        __syncthreads();
#pragma unroll
        for (int j = 0; j < 8; j++) {
            int i4 = t + 128 * j;        // 1024 float4 slots = 256 nodes x 16 floats
            int nloc = i4 >> 2;
            int k4 = (i4 & 3) * 4;
            int nn = node0 + nloc;
            float4 v = (nn < n) ? *(const float4*)&x[(size_t)nn * 256 + kk + k4]
                                : make_float4(0.f, 0.f, 0.f, 0.f);
            xs[k4 + 0][nloc] = v.x;
            xs[k4 + 1][nloc] = v.y;
            xs[k4 + 2][nloc] = v.z;
            xs[k4 + 3][nloc] = v.w;
        }
        __syncthreads();
#pragma unroll
        for (int k = 0; k < 16; k++) {
            float xa = xs[k][t];
            float xb = xs[k][t + 128];
            const float4* wr = (const float4*)&Ws[(kk + k) * 16];
            float4 w0 = wr[0], w1 = wr[1], w2 = wr[2], w3 = wr[3];
            accA[0]  += xa * w0.x; accA[1]  += xa * w0.y; accA[2]  += xa * w0.z; accA[3]  += xa * w0.w;
            accA[4]  += xa * w1.x; accA[5]  += xa * w1.y; accA[6]  += xa * w1.z; accA[7]  += xa * w1.w;
            accA[8]  += xa * w2.x; accA[9]  += xa * w2.y; accA[10] += xa * w2.z; accA[11] += xa * w2.w;
            accA[12] += xa * w3.x; accA[13] += xa * w3.y; accA[14] += xa * w3.z; accA[15] += xa * w3.w;
            accB[0]  += xb * w0.x; accB[1]  += xb * w0.y; accB[2]  += xb * w0.z; accB[3]  += xb * w0.w;
            accB[4]  += xb * w1.x; accB[5]  += xb * w1.y; accB[6]  += xb * w1.z; accB[7]  += xb * w1.w;
            accB[8]  += xb * w2.x; accB[9]  += xb * w2.y; accB[10] += xb * w2.z; accB[11] += xb * w2.w;
            accB[12] += xb * w3.x; accB[13] += xb * w3.y; accB[14] += xb * w3.z; accB[15] += xb * w3.w;
        }
    }
    int nodeA = node0 + t;
    if (nodeA < n) {
        float4* hp = (float4*)(g_h1raw + (size_t)nodeA * 16);
#pragma unroll
        for (int q = 0; q < 4; q++)
            hp[q] = make_float4(accA[4 * q], accA[4 * q + 1], accA[4 * q + 2], accA[4 * q + 3]);
    }
    int nodeB = node0 + t + 128;
    if (nodeB < n) {
        float4* hp = (float4*)(g_h1raw + (size_t)nodeB * 16);
#pragma unroll
        for (int q = 0; q < 4; q++)
            hp[q] = make_float4(accB[4 * q], accB[4 * q + 1], accB[4 * q + 2], accB[4 * q + 3]);
    }
}

// kernel 3: scatter edges into fixed-slab CSR as (w, row).
// Launched with PDL (programmaticStreamSerialization) to overlap gemmraw.
// No smem -> its 256-thread blocks fill the thread slots gemm leaves free.
__global__ __launch_bounds__(256) void scatter_kernel(const void* __restrict__ idxv,
                                                      const float* __restrict__ w, int E) {
    int e = blockIdx.x * blockDim.x + threadIdx.x;
    if (e >= E) return;
    int row, col;
    if (g_is64) {
        const long long* p = (const long long*)idxv;
        row = (int)p[e];
        col = (int)p[(size_t)E + e];
    } else {
        const int* p = (const int*)idxv;
        row = p[e];
        col = p[E + e];
    }
    int r = atomicAdd(&g_cnt[col], 1);
    if (r < CAP)
        g_csr[(size_t)col * CAP + r] =
            ((unsigned long long)__float_as_uint(w[e]) << 32) | (unsigned int)row;
}

// kernel 4: fused deg + scale. Warp per node: weighted degree from slab
// (coalesced), rsqrt, then scale h1raw -> h1s (4 lanes x float4).
__global__ __launch_bounds__(256) void degscale_kernel(int n) {
    int node = (blockIdx.x * blockDim.x + threadIdx.x) >> 5;
    if (node >= n) return;
    int lane = threadIdx.x & 31;
    int cnt = min(g_cnt[node], CAP);
    size_t base = (size_t)node * CAP;
    float s = 0.f;
    for (int e = lane; e < cnt; e += 32)
        s += __uint_as_float((unsigned int)(g_csr[base + e] >> 32));
#pragma unroll
    for (int d = 16; d > 0; d >>= 1)
        s += __shfl_xor_sync(0xffffffff, s, d);   // all lanes hold the sum
    float di = rsqrtf(1.0f + s);                  // +1 = self-loop weight
    if (lane == 0) g_dinv[node] = di;
    if (lane < 4) {
        float4 v = ((const float4*)(g_h1raw + (size_t)node * 16))[lane];
        ((float4*)(g_h1s + (size_t)node * 16))[lane] =
            make_float4(v.x * di, v.y * di, v.z * di, v.w * di);
    }
}

// kernel 5: layer-1 aggregation. One warp per node, 8 edge-slots x 4 feature-lanes.
// r' = relu(dinv*(sum_e h1s[row]*w + h1s[self]) + b1) * dinv
__global__ __launch_bounds__(256) void agg1_kernel(const float* __restrict__ b1, int n) {
    int node = (blockIdx.x * blockDim.x + threadIdx.x) >> 5;
    if (node >= n) return;
    int lane = threadIdx.x & 31;
    int es = lane >> 2, f = lane & 3;

    size_t base = (size_t)node * CAP;
    int cnt = min(g_cnt[node], CAP);
    float4 acc = make_float4(0.f, 0.f, 0.f, 0.f);
    for (int e = es; e < cnt; e += 8) {
        unsigned long long v = g_csr[base + e];
        int row = (int)(unsigned int)(v & 0xffffffffu);
        float w = __uint_as_float((unsigned int)(v >> 32));
        float4 h = ((const float4*)(g_h1s + (size_t)row * 16))[f];
        acc.x += h.x * w; acc.y += h.y * w;
        acc.z += h.z * w; acc.w += h.w * w;
    }
#pragma unroll
    for (int s = 16; s >= 4; s >>= 1) {
        acc.x += __shfl_down_sync(0xffffffff, acc.x, s);
        acc.y += __shfl_down_sync(0xffffffff, acc.y, s);
        acc.z += __shfl_down_sync(0xffffffff, acc.z, s);
        acc.w += __shfl_down_sync(0xffffffff, acc.w, s);
    }
    if (es == 0) {
        float di = g_dinv[node];
        float4 h = ((const float4*)(g_h1s + (size_t)node * 16))[f];
        float4 b = ((const float4*)b1)[f];
        acc.x = fmaxf((acc.x + h.x) * di + b.x, 0.f) * di;
        acc.y = fmaxf((acc.y + h.y) * di + b.y, 0.f) * di;
        acc.z = fmaxf((acc.z + h.z) * di + b.z, 0.f) * di;
        acc.w = fmaxf((acc.w + h.w) * di + b.w, 0.f) * di;
        ((float4*)(g_r + (size_t)node * 16))[f] = acc;
    }
}

// kernel 6: layer-2 aggregation fused with W2 GEMM + log_softmax.
__global__ __launch_bounds__(256) void agg2final_kernel(const float* __restrict__ W2,
                                                        const float* __restrict__ b2,
                                                        float* __restrict__ out, int n) {
    __shared__ float W2s[16 * 40];
    __shared__ float b2s[40];
    __shared__ float sh[8][16];
    int t = threadIdx.x;
    for (int i = t; i < 640; i += 256) W2s[i] = W2[i];
    if (t < 40) b2s[t] = b2[t];
    __syncthreads();

    int warp = t >> 5;
    int lane = t & 31;
    int node = blockIdx.x * 8 + warp;
    if (node >= n) return;
    int es = lane >> 2, f = lane & 3;

    size_t base = (size_t)node * CAP;
    int cnt = min(g_cnt[node], CAP);
    float4 acc = make_float4(0.f, 0.f, 0.f, 0.f);
    for (int e = es; e < cnt; e += 8) {
        unsigned long long v = g_csr[base + e];
        int row = (int)(unsigned int)(v & 0xffffffffu);
        float w = __uint_as_float((unsigned int)(v >> 32));
        float4 h = ((const float4*)(g_r + (size_t)row * 16))[f];
        acc.x += h.x * w; acc.y += h.y * w;
        acc.z += h.z * w; acc.w += h.w * w;
    }
#pragma unroll
    for (int s = 16; s >= 4; s >>= 1) {
        acc.x += __shfl_down_sync(0xffffffff, acc.x, s);
        acc.y += __shfl_down_sync(0xffffffff, acc.y, s);
        acc.z += __shfl_down_sync(0xffffffff, acc.z, s);
        acc.w += __shfl_down_sync(0xffffffff, acc.w, s);
    }
    if (es == 0) {
        float di = g_dinv[node];
        float4 h = ((const float4*)(g_r + (size_t)node * 16))[f];
        acc.x = (acc.x + h.x) * di;
        acc.y = (acc.y + h.y) * di;
        acc.z = (acc.z + h.z) * di;
        acc.w = (acc.w + h.w) * di;
        ((float4*)&sh[warp][0])[f] = acc;
    }
    __syncwarp();

    // 40 logits distributed over the warp (lane -> out[lane], lane<8 -> out[lane+32])
    float v0 = b2s[lane];
    float v1 = (lane < 8) ? b2s[lane + 32] : -1e30f;
#pragma unroll
    for (int k = 0; k < 16; k++) {
        float hv = sh[warp][k];
        v0 += hv * W2s[k * 40 + lane];
        if (lane < 8) v1 += hv * W2s[k * 40 + lane + 32];
    }
    float m = fmaxf(v0, v1);
#pragma unroll
    for (int s = 16; s > 0; s >>= 1)
        m = fmaxf(m, __shfl_xor_sync(0xffffffff, m, s));
    float sum = __expf(v0 - m) + ((lane < 8) ? __expf(v1 - m) : 0.f);
#pragma unroll
    for (int s = 16; s > 0; s >>= 1)
        sum += __shfl_xor_sync(0xffffffff, sum, s);
    float l = m + __logf(sum);
    out[(size_t)node * 40 + lane] = v0 - l;
    if (lane < 8) out[(size_t)node * 40 + 32 + lane] = v1 - l;
}

extern "C" void kernel_launch(void* const* d_in, const int* in_sizes, int n_in,
                              void* d_out, int out_size) {
    const float* x  = (const float*)d_in[0];
    const void*  ei = d_in[1];
    const float* ew = (const float*)d_in[2];
    const float* W1 = (const float*)d_in[3];
    const float* b1 = (const float*)d_in[4];
    const float* W2 = (const float*)d_in[5];
    const float* b2 = (const float*)d_in[6];
    float* out = (float*)d_out;

    int n = in_sizes[0] / 256;   // N nodes
    int E = in_sizes[2];         // edges

    int nb = (n + 255) / 256;

    initdet_kernel<<<nb, 256>>>((const unsigned int*)ei, n);
    gemmraw_kernel<<<(n + 255) / 256, 128>>>(x, W1, n);

    // scatter with PDL: may launch while gemmraw is still resident (overlap).
    {
        cudaLaunchConfig_t cfg = {};
        cfg.gridDim  = dim3((unsigned)((E + 255) / 256), 1, 1);
        cfg.blockDim = dim3(256, 1, 1);
        cfg.dynamicSmemBytes = 0;
        cfg.stream = 0;
        cudaLaunchAttribute attr[1];
        attr[0].id = cudaLaunchAttributeProgrammaticStreamSerialization;
        attr[0].val.programmaticStreamSerializationAllowed = 1;
        cfg.attrs = attr;
        cfg.numAttrs = 1;
        cudaLaunchKernelEx(&cfg, scatter_kernel, ei, ew, E);
    }

    degscale_kernel<<<(n + 7) / 8, 256>>>(n);
    agg1_kernel<<<(n + 7) / 8, 256>>>(b1, n);
    agg2final_kernel<<<(n + 7) / 8, 256>>>(W2, b2, out, n);
}